// round 6
// baseline (speedup 1.0000x reference)
#include <cuda_runtime.h>
#include <cuda_bf16.h>
#include <mma.h>
#include <math.h>
#include <stdint.h>

using namespace nvcuda;

// ===========================================================================
// DLRM forward. bf16 wmma (m16n16k16 HMMA) GEMMs, fp32 accumulate.
// 3-stage cp.async pipeline, single barrier per k-tile.
// ===========================================================================

#define BATCH      16384
#define EMB_DIM    128
#define TABLE_SIZE 100000
#define NUM_CAT    26
#define NUM_FEATS  27
#define TOP_IN     480
#define TOP_IN_P   512          // padded K for top layer 1

// ------------------------- scratch (device globals) ------------------------
__device__ __nv_bfloat16 g_h1[BATCH * 512];
__device__ __nv_bfloat16 g_h2[BATCH * 256];
__device__ __nv_bfloat16 g_bot[BATCH * 128];
__device__ __nv_bfloat16 g_x [BATCH * TOP_IN_P];
__device__ __nv_bfloat16 g_t1[BATCH * 1024];
__device__ __nv_bfloat16 g_t2[BATCH * 1024];
__device__ __nv_bfloat16 g_t3[BATCH * 512];
__device__ __nv_bfloat16 g_t4[BATCH * 256];
// bf16-rounded weights
__device__ __nv_bfloat16 g_bw2r[256 * 512];
__device__ __nv_bfloat16 g_bw3r[128 * 256];
__device__ __nv_bfloat16 g_tw1r[1024 * TOP_IN_P];   // zero-padded K
__device__ __nv_bfloat16 g_tw2r[1024 * 1024];
__device__ __nv_bfloat16 g_tw3r[512 * 1024];
__device__ __nv_bfloat16 g_tw4r[256 * 512];

// ------------------------------ helpers ------------------------------------
__device__ __forceinline__ uint32_t smem_u32(const void* p) {
    return (uint32_t)__cvta_generic_to_shared(p);
}
#define CP_ASYNC16(dst, src) \
    asm volatile("cp.async.cg.shared.global [%0], [%1], 16;" :: "r"(dst), "l"(src))
__device__ __forceinline__ void cp_commit() { asm volatile("cp.async.commit_group;"); }
__device__ __forceinline__ void cp_wait1() { asm volatile("cp.async.wait_group 1;"); }
__device__ __forceinline__ void cp_wait0() { asm volatile("cp.async.wait_group 0;"); }

// ===========================================================================
// bf16 wmma GEMM:  C[M,N] = relu(A[M,K] @ W[N,K]^T + bias), C in bf16
// CTA 128x128, BK=64, 3-stage cp.async, 8 warps each 64x32.
// Requires M%128==0, N%128==0, K%64==0.
// smem stage: (128+128) rows x 144B = 36864 B; 3 stages = 110592 B.
// ===========================================================================
#define LDM 72                               // bf16 elems; 144 B row stride
#define STAGE_ELEMS (2 * 128 * LDM)          // bf16 elems per stage
#define STAGE_BYTES (STAGE_ELEMS * 2)        // 36864
#define GEMM_SMEM   (3 * STAGE_BYTES)        // 110592

__global__ __launch_bounds__(256, 2)
void bf16_gemm(const __nv_bfloat16* __restrict__ A,
               const __nv_bfloat16* __restrict__ W,
               const float* __restrict__ bias,
               __nv_bfloat16* __restrict__ C,
               int N, int K) {
    extern __shared__ __nv_bfloat16 smem[];
    const int tid = threadIdx.x;
    const int warp = tid >> 5;
    const int bm = blockIdx.y * 128;
    const int bn = blockIdx.x * 128;
    const int wm = warp >> 2;        // 0..1 -> 64-row half
    const int wn = warp & 3;         // 0..3 -> 32-col quarter
    const uint32_t sb = smem_u32(smem);

    wmma::fragment<wmma::accumulator, 16, 16, 16, float> cf[4][2];
#pragma unroll
    for (int i = 0; i < 4; i++)
#pragma unroll
        for (int j = 0; j < 2; j++) wmma::fill_fragment(cf[i][j], 0.0f);

    const int T = K / 64;

    // loader: per matrix 128 rows x 8 chunks(16B) = 1024; 256 thr -> 4 each
    auto load_stage = [&](int t) {
        const int s = t % 3;
        const int k0 = t * 64;
        const uint32_t abase = sb + (uint32_t)s * STAGE_BYTES;
        const uint32_t bbase = abase + 128u * LDM * 2u;
#pragma unroll
        for (int i = 0; i < 4; i++) {
            int idx = tid + i * 256;
            int r = idx >> 3, c = idx & 7;
            CP_ASYNC16(abase + (uint32_t)(r * LDM + c * 8) * 2u,
                       A + (size_t)(bm + r) * K + k0 + c * 8);
        }
#pragma unroll
        for (int i = 0; i < 4; i++) {
            int idx = tid + i * 256;
            int r = idx >> 3, c = idx & 7;
            CP_ASYNC16(bbase + (uint32_t)(r * LDM + c * 8) * 2u,
                       W + (size_t)(bn + r) * K + k0 + c * 8);
        }
        cp_commit();
    };

    load_stage(0);
    if (T > 1) load_stage(1);

    for (int t = 0; t < T; t++) {
        // stage t arrived: keep at most the (t+1) group outstanding
        if (t + 1 < T) cp_wait1(); else cp_wait0();
        __syncthreads();      // all warps done with stage t-1 & see stage t
        if (t + 2 < T) load_stage(t + 2);   // writes buf (t+2)%3 == (t-1)%3: safe

        const __nv_bfloat16* a = smem + (size_t)(t % 3) * STAGE_ELEMS;
        const __nv_bfloat16* b = a + 128 * LDM;
#pragma unroll
        for (int kk = 0; kk < 64; kk += 16) {
            wmma::fragment<wmma::matrix_a, 16, 16, 16, __nv_bfloat16, wmma::row_major> af[4];
            wmma::fragment<wmma::matrix_b, 16, 16, 16, __nv_bfloat16, wmma::col_major> bf[2];
#pragma unroll
            for (int i = 0; i < 4; i++)
                wmma::load_matrix_sync(af[i], a + (wm * 64 + i * 16) * LDM + kk, LDM);
#pragma unroll
            for (int j = 0; j < 2; j++)
                wmma::load_matrix_sync(bf[j], b + (wn * 32 + j * 16) * LDM + kk, LDM);
#pragma unroll
            for (int i = 0; i < 4; i++)
#pragma unroll
                for (int j = 0; j < 2; j++)
                    wmma::mma_sync(cf[i][j], af[i], bf[j], cf[i][j]);
        }
    }
    __syncthreads();   // protect smem reuse by epilogue

    // ---------------- epilogue: fragments -> smem(fp32) -> bf16 gmem -------
    float* cs = (float*)smem;   // [128][132] fp32 = 67584 B < 110592
#pragma unroll
    for (int i = 0; i < 4; i++)
#pragma unroll
        for (int j = 0; j < 2; j++)
            wmma::store_matrix_sync(cs + (size_t)(wm * 64 + i * 16) * 132 + wn * 32 + j * 16,
                                    cf[i][j], 132, wmma::mem_row_major);
    __syncthreads();

    {
        const int row = tid >> 1, h = tid & 1;       // 2 threads/row, 64 cols each
        const float* src = cs + (size_t)row * 132 + h * 64;
        __nv_bfloat16* dst = C + (size_t)(bm + row) * N + bn + h * 64;
        const float* bsrc = bias + bn + h * 64;
#pragma unroll
        for (int q = 0; q < 8; q++) {               // 8 cols per iter -> 16B store
            float4 v0 = *(const float4*)(src + q * 8);
            float4 v1 = *(const float4*)(src + q * 8 + 4);
            float4 b0 = *(const float4*)(bsrc + q * 8);
            float4 b1 = *(const float4*)(bsrc + q * 8 + 4);
            v0.x += b0.x; v0.y += b0.y; v0.z += b0.z; v0.w += b0.w;
            v1.x += b1.x; v1.y += b1.y; v1.z += b1.z; v1.w += b1.w;
            v0.x = v0.x > 0.f ? v0.x : 0.f;
            v0.y = v0.y > 0.f ? v0.y : 0.f;
            v0.z = v0.z > 0.f ? v0.z : 0.f;
            v0.w = v0.w > 0.f ? v0.w : 0.f;
            v1.x = v1.x > 0.f ? v1.x : 0.f;
            v1.y = v1.y > 0.f ? v1.y : 0.f;
            v1.z = v1.z > 0.f ? v1.z : 0.f;
            v1.w = v1.w > 0.f ? v1.w : 0.f;
            __nv_bfloat162 p0 = __floats2bfloat162_rn(v0.x, v0.y);
            __nv_bfloat162 p1 = __floats2bfloat162_rn(v0.z, v0.w);
            __nv_bfloat162 p2 = __floats2bfloat162_rn(v1.x, v1.y);
            __nv_bfloat162 p3 = __floats2bfloat162_rn(v1.z, v1.w);
            uint4 pk;
            pk.x = *(uint32_t*)&p0; pk.y = *(uint32_t*)&p1;
            pk.z = *(uint32_t*)&p2; pk.w = *(uint32_t*)&p3;
            *(uint4*)(dst + q * 8) = pk;
        }
    }
}

// ===========================================================================
// fp32 SGEMM for the K=13 bottom layer 1 -> bf16 out.
// ===========================================================================
__global__ __launch_bounds__(256, 2)
void sgemm_l1(const float* __restrict__ A, const float* __restrict__ W,
              const float* __restrict__ bias, __nv_bfloat16* __restrict__ C,
              int N, int K) {
    __shared__ float As[8][132];
    __shared__ float Bs[8][132];
    const int tid = threadIdx.x;
    const int bm = blockIdx.y * 128, bn = blockIdx.x * 128;
    const int tx = tid & 15, ty = tid >> 4;
    const int lk = tid & 7, lr = tid >> 3;

    float acc[8][8];
#pragma unroll
    for (int i = 0; i < 8; i++)
#pragma unroll
        for (int j = 0; j < 8; j++) acc[i][j] = 0.f;

    for (int k0 = 0; k0 < K; k0 += 8) {
        const int kk = k0 + lk;
        const bool kv = (kk < K);
#pragma unroll
        for (int p = 0; p < 4; p++) {
            const int row = lr + p * 32;
            As[lk][row] = kv ? A[(size_t)(bm + row) * K + kk] : 0.f;
            Bs[lk][row] = kv ? W[(size_t)(bn + row) * K + kk] : 0.f;
        }
        __syncthreads();
#pragma unroll
        for (int k = 0; k < 8; k++) {
            float4 a0 = *(const float4*)&As[k][ty * 4];
            float4 a1 = *(const float4*)&As[k][64 + ty * 4];
            float4 b0 = *(const float4*)&Bs[k][tx * 4];
            float4 b1 = *(const float4*)&Bs[k][64 + tx * 4];
            float a[8] = {a0.x, a0.y, a0.z, a0.w, a1.x, a1.y, a1.z, a1.w};
            float b[8] = {b0.x, b0.y, b0.z, b0.w, b1.x, b1.y, b1.z, b1.w};
#pragma unroll
            for (int i = 0; i < 8; i++)
#pragma unroll
                for (int j = 0; j < 8; j++)
                    acc[i][j] += a[i] * b[j];
        }
        __syncthreads();
    }
    const int rbase[2] = {bm + ty * 4, bm + 64 + ty * 4};
    const int cbase[2] = {bn + tx * 4, bn + 64 + tx * 4};
#pragma unroll
    for (int jh = 0; jh < 2; jh++) {
        const int col = cbase[jh];
        float4 bv = *(const float4*)&bias[col];
#pragma unroll
        for (int ih = 0; ih < 2; ih++) {
#pragma unroll
            for (int i = 0; i < 4; i++) {
                const int row = rbase[ih] + i;
                float4 v;
                v.x = acc[ih * 4 + i][jh * 4 + 0] + bv.x;
                v.y = acc[ih * 4 + i][jh * 4 + 1] + bv.y;
                v.z = acc[ih * 4 + i][jh * 4 + 2] + bv.z;
                v.w = acc[ih * 4 + i][jh * 4 + 3] + bv.w;
                v.x = v.x > 0.f ? v.x : 0.f;
                v.y = v.y > 0.f ? v.y : 0.f;
                v.z = v.z > 0.f ? v.z : 0.f;
                v.w = v.w > 0.f ? v.w : 0.f;
                __nv_bfloat162 p0 = __floats2bfloat162_rn(v.x, v.y);
                __nv_bfloat162 p1 = __floats2bfloat162_rn(v.z, v.w);
                uint2 pk; pk.x = *(uint32_t*)&p0; pk.y = *(uint32_t*)&p1;
                *(uint2*)&C[(size_t)row * N + col] = pk;
            }
        }
    }
}

// ===========================================================================
// Interaction: 3 samples/CTA; gram in fp32; bf16 output (padded to 512).
// ===========================================================================
__global__ __launch_bounds__(96)
void interact2(const __nv_bfloat16* __restrict__ bottom,
               const int* __restrict__ cat,
               const float* __restrict__ emb,
               __nv_bfloat16* __restrict__ x) {
    __shared__ float feats[3][NUM_FEATS][132];
    const int tid = threadIdx.x;
    const int b0 = blockIdx.x * 3;

    for (int idx = tid; idx < 3 * NUM_FEATS * 32; idx += 96) {
        const int s = idx / (NUM_FEATS * 32);
        const int rem = idx % (NUM_FEATS * 32);
        const int r = rem >> 5, q = rem & 31;
        const int b = b0 + s;
        if (b >= BATCH) continue;
        float4 v;
        if (r == 0) {
            uint2 raw = *(const uint2*)(bottom + (size_t)b * 128 + q * 4);
            __nv_bfloat162 p0 = *(__nv_bfloat162*)&raw.x;
            __nv_bfloat162 p1 = *(__nv_bfloat162*)&raw.y;
            v.x = __bfloat162float(p0.x); v.y = __bfloat162float(p0.y);
            v.z = __bfloat162float(p1.x); v.w = __bfloat162float(p1.y);
        } else {
            const int ci = cat[(size_t)(r - 1) * BATCH + b];
            v = *(const float4*)(emb + ((size_t)(r - 1) * TABLE_SIZE + ci) * 128 + q * 4);
        }
        feats[s][r][q * 4 + 0] = v.x;
        feats[s][r][q * 4 + 1] = v.y;
        feats[s][r][q * 4 + 2] = v.z;
        feats[s][r][q * 4 + 3] = v.w;
    }
    __syncthreads();

    {   // bottom copy (cols 0..127) + zero pad (cols 479..511)
        const int s = tid >> 5, q = tid & 31;
        const int b = b0 + s;
        if (b < BATCH) {
            __nv_bfloat16* xb = x + (size_t)b * TOP_IN_P;
            float4 v = *(const float4*)&feats[s][0][q * 4];
            __nv_bfloat162 p0 = __floats2bfloat162_rn(v.x, v.y);
            __nv_bfloat162 p1 = __floats2bfloat162_rn(v.z, v.w);
            uint2 pk; pk.x = *(uint32_t*)&p0; pk.y = *(uint32_t*)&p1;
            *(uint2*)(xb + q * 4) = pk;
            if (q == 0) {
                for (int c = TOP_IN - 1; c < TOP_IN_P; c++)
                    xb[c] = __float2bfloat16(0.f);
            }
        }
    }

    if (tid < 84) {
        const int s = tid / 28, blk = tid % 28;
        const int b = b0 + s;
        if (b < BATCH) {
            int R = 0;
            while ((R + 1) * (R + 2) / 2 <= blk) R++;
            const int Cc = blk - R * (R + 1) / 2;
            const int r0 = 4 * R, c0 = 4 * Cc;
            const float (*fs)[132] = feats[s];

            float acc[4][4];
#pragma unroll
            for (int i = 0; i < 4; i++)
#pragma unroll
                for (int j = 0; j < 4; j++) acc[i][j] = 0.f;

            const int ra[4] = {r0 < 27 ? r0 : 0, r0 + 1 < 27 ? r0 + 1 : 0,
                               r0 + 2 < 27 ? r0 + 2 : 0, r0 + 3 < 27 ? r0 + 3 : 0};
            const int ca[4] = {c0 < 27 ? c0 : 0, c0 + 1 < 27 ? c0 + 1 : 0,
                               c0 + 2 < 27 ? c0 + 2 : 0, c0 + 3 < 27 ? c0 + 3 : 0};

            for (int k = 0; k < 128; k += 4) {
                float4 av[4], bv[4];
#pragma unroll
                for (int i = 0; i < 4; i++) av[i] = *(const float4*)&fs[ra[i]][k];
#pragma unroll
                for (int j = 0; j < 4; j++) bv[j] = *(const float4*)&fs[ca[j]][k];
#pragma unroll
                for (int i = 0; i < 4; i++)
#pragma unroll
                    for (int j = 0; j < 4; j++)
                        acc[i][j] += av[i].x * bv[j].x + av[i].y * bv[j].y +
                                     av[i].z * bv[j].z + av[i].w * bv[j].w;
            }
            __nv_bfloat16* xb = x + (size_t)b * TOP_IN_P;
#pragma unroll
            for (int i = 0; i < 4; i++)
#pragma unroll
                for (int j = 0; j < 4; j++) {
                    const int r = r0 + i, c = c0 + j;
                    if (r < NUM_FEATS && c < r)
                        xb[128 + r * (r - 1) / 2 + c] = __float2bfloat16(acc[i][j]);
                }
        }
    }
}

// ===========================================================================
// ONE kernel rounding all weights (keeps launch #6 = big GEMM for ncu -s 5).
// Segments: bw2(131072), bw3(32768), tw1 padded(1024x512 from 1024x480),
//           tw2(1048576), tw3(524288), tw4(131072)
// ===========================================================================
#define RW_N0 131072            // bw2
#define RW_N1 32768             // bw3
#define RW_N2 (1024 * TOP_IN_P) // tw1 padded = 524288
#define RW_N3 1048576           // tw2
#define RW_N4 524288            // tw3
#define RW_N5 131072            // tw4
#define RW_TOTAL (RW_N0 + RW_N1 + RW_N2 + RW_N3 + RW_N4 + RW_N5)

__global__ __launch_bounds__(256)
void round_all(const float* __restrict__ bw2, const float* __restrict__ bw3,
               const float* __restrict__ tw1, const float* __restrict__ tw2,
               const float* __restrict__ tw3, const float* __restrict__ tw4,
               __nv_bfloat16* __restrict__ d0, __nv_bfloat16* __restrict__ d1,
               __nv_bfloat16* __restrict__ d2, __nv_bfloat16* __restrict__ d3,
               __nv_bfloat16* __restrict__ d4, __nv_bfloat16* __restrict__ d5) {
    int i = blockIdx.x * blockDim.x + threadIdx.x;
    if (i >= RW_TOTAL) return;
    if (i < RW_N0) { d0[i] = __float2bfloat16(bw2[i]); return; }
    i -= RW_N0;
    if (i < RW_N1) { d1[i] = __float2bfloat16(bw3[i]); return; }
    i -= RW_N1;
    if (i < RW_N2) {
        int n = i / TOP_IN_P, k = i % TOP_IN_P;
        d2[i] = (k < TOP_IN) ? __float2bfloat16(tw1[n * TOP_IN + k])
                             : __float2bfloat16(0.f);
        return;
    }
    i -= RW_N2;
    if (i < RW_N3) { d3[i] = __float2bfloat16(tw2[i]); return; }
    i -= RW_N3;
    if (i < RW_N4) { d4[i] = __float2bfloat16(tw3[i]); return; }
    i -= RW_N4;
    d5[i] = __float2bfloat16(tw4[i]);
}

// ===========================================================================
// Final layer: sigmoid(dot(t4_bf16, w5_fp32) + b5). Warp per sample.
// ===========================================================================
__global__ __launch_bounds__(256)
void final_layer(const __nv_bfloat16* __restrict__ A,
                 const float* __restrict__ w5,
                 const float* __restrict__ b5, float* __restrict__ out) {
    const int gwarp = (blockIdx.x * blockDim.x + threadIdx.x) >> 5;
    const int lane = threadIdx.x & 31;
    if (gwarp >= BATCH) return;
    uint4 raw = *(const uint4*)(A + (size_t)gwarp * 256 + lane * 8);
    const float4* w4 = (const float4*)(w5 + lane * 8);
    float4 w0 = w4[0], w1 = w4[1];
    __nv_bfloat162 p0 = *(__nv_bfloat162*)&raw.x;
    __nv_bfloat162 p1 = *(__nv_bfloat162*)&raw.y;
    __nv_bfloat162 p2 = *(__nv_bfloat162*)&raw.z;
    __nv_bfloat162 p3 = *(__nv_bfloat162*)&raw.w;
    float s = __bfloat162float(p0.x) * w0.x + __bfloat162float(p0.y) * w0.y +
              __bfloat162float(p1.x) * w0.z + __bfloat162float(p1.y) * w0.w +
              __bfloat162float(p2.x) * w1.x + __bfloat162float(p2.y) * w1.y +
              __bfloat162float(p3.x) * w1.z + __bfloat162float(p3.y) * w1.w;
#pragma unroll
    for (int o = 16; o; o >>= 1) s += __shfl_xor_sync(0xffffffffu, s, o);
    if (lane == 0) out[gwarp] = 1.f / (1.f + expf(-(s + b5[0])));
}

// ===========================================================================
extern "C" void kernel_launch(void* const* d_in, const int* in_sizes, int n_in,
                              void* d_out, int out_size) {
    const float* num = (const float*)d_in[0];
    const int*   cat = (const int*)  d_in[1];
    const float* emb = (const float*)d_in[2];
    const float* bw1 = (const float*)d_in[3];
    const float* bb1 = (const float*)d_in[4];
    const float* bw2 = (const float*)d_in[5];
    const float* bb2 = (const float*)d_in[6];
    const float* bw3 = (const float*)d_in[7];
    const float* bb3 = (const float*)d_in[8];
    const float* tw1 = (const float*)d_in[9];
    const float* tb1 = (const float*)d_in[10];
    const float* tw2 = (const float*)d_in[11];
    const float* tb2 = (const float*)d_in[12];
    const float* tw3 = (const float*)d_in[13];
    const float* tb3 = (const float*)d_in[14];
    const float* tw4 = (const float*)d_in[15];
    const float* tb4 = (const float*)d_in[16];
    const float* tw5 = (const float*)d_in[17];
    const float* tb5 = (const float*)d_in[18];
    float* out = (float*)d_out;

    __nv_bfloat16 *h1, *h2, *bot, *x, *t1, *t2, *t3, *t4;
    __nv_bfloat16 *bw2r, *bw3r, *tw1r, *tw2r, *tw3r, *tw4r;
    cudaGetSymbolAddress((void**)&h1,  g_h1);
    cudaGetSymbolAddress((void**)&h2,  g_h2);
    cudaGetSymbolAddress((void**)&bot, g_bot);
    cudaGetSymbolAddress((void**)&x,   g_x);
    cudaGetSymbolAddress((void**)&t1,  g_t1);
    cudaGetSymbolAddress((void**)&t2,  g_t2);
    cudaGetSymbolAddress((void**)&t3,  g_t3);
    cudaGetSymbolAddress((void**)&t4,  g_t4);
    cudaGetSymbolAddress((void**)&bw2r, g_bw2r);
    cudaGetSymbolAddress((void**)&bw3r, g_bw3r);
    cudaGetSymbolAddress((void**)&tw1r, g_tw1r);
    cudaGetSymbolAddress((void**)&tw2r, g_tw2r);
    cudaGetSymbolAddress((void**)&tw3r, g_tw3r);
    cudaGetSymbolAddress((void**)&tw4r, g_tw4r);

    cudaFuncSetAttribute(bf16_gemm, cudaFuncAttributeMaxDynamicSharedMemorySize, GEMM_SMEM);

    // launch 1: all weight rounding in one kernel
    round_all<<<(RW_TOTAL + 255) / 256, 256>>>(bw2, bw3, tw1, tw2, tw3, tw4,
                                               bw2r, bw3r, tw1r, tw2r, tw3r, tw4r);

    const int MB = BATCH / 128;  // 128

    // launches 2-4: bottom MLP
    sgemm_l1<<<dim3(4, MB), 256>>>(num, bw1, bb1, h1, 512, 13);
    bf16_gemm<<<dim3(2, MB), 256, GEMM_SMEM>>>(h1, bw2r, bb2, h2, 256, 512);
    bf16_gemm<<<dim3(1, MB), 256, GEMM_SMEM>>>(h2, bw3r, bb3, bot, 128, 256);

    // launch 5: embedding gather + interaction
    interact2<<<(BATCH + 2) / 3, 96>>>(bot, cat, emb, x);

    // launch 6 (ncu -s 5 profiles this one): top layer 1
    bf16_gemm<<<dim3(8, MB), 256, GEMM_SMEM>>>(x,  tw1r, tb1, t1, 1024, TOP_IN_P);
    bf16_gemm<<<dim3(8, MB), 256, GEMM_SMEM>>>(t1, tw2r, tb2, t2, 1024, 1024);
    bf16_gemm<<<dim3(4, MB), 256, GEMM_SMEM>>>(t2, tw3r, tb3, t3, 512, 1024);
    bf16_gemm<<<dim3(2, MB), 256, GEMM_SMEM>>>(t3, tw4r, tb4, t4, 256, 512);

    // final dot + sigmoid
    final_layer<<<(BATCH * 32 + 255) / 256, 256>>>(t4, tw5, tb5, out);
}

// round 7
// speedup vs baseline: 1.0930x; 1.0930x over previous
#include <cuda_runtime.h>
#include <cuda_bf16.h>
#include <mma.h>
#include <math.h>
#include <stdint.h>

using namespace nvcuda;

// ===========================================================================
// DLRM forward. bf16 wmma GEMMs (BK=32, 4-stage cp.async, 2 CTAs/SM) +
// tensor-core interaction (warp-per-sample gram).
// ===========================================================================

#define BATCH      16384
#define EMB_DIM    128
#define TABLE_SIZE 100000
#define NUM_CAT    26
#define NUM_FEATS  27
#define TOP_IN     480
#define TOP_IN_P   512

// ------------------------- scratch (device globals) ------------------------
__device__ __nv_bfloat16 g_h1[BATCH * 512];
__device__ __nv_bfloat16 g_h2[BATCH * 256];
__device__ __nv_bfloat16 g_bot[BATCH * 128];
__device__ __nv_bfloat16 g_x [BATCH * TOP_IN_P];
__device__ __nv_bfloat16 g_t1[BATCH * 1024];
__device__ __nv_bfloat16 g_t2[BATCH * 1024];
__device__ __nv_bfloat16 g_t3[BATCH * 512];
__device__ __nv_bfloat16 g_t4[BATCH * 256];
__device__ __nv_bfloat16 g_bw2r[256 * 512];
__device__ __nv_bfloat16 g_bw3r[128 * 256];
__device__ __nv_bfloat16 g_tw1r[1024 * TOP_IN_P];
__device__ __nv_bfloat16 g_tw2r[1024 * 1024];
__device__ __nv_bfloat16 g_tw3r[512 * 1024];
__device__ __nv_bfloat16 g_tw4r[256 * 512];

// ------------------------------ helpers ------------------------------------
__device__ __forceinline__ uint32_t smem_u32(const void* p) {
    return (uint32_t)__cvta_generic_to_shared(p);
}
#define CP_ASYNC16(dst, src) \
    asm volatile("cp.async.cg.shared.global [%0], [%1], 16;" :: "r"(dst), "l"(src))
__device__ __forceinline__ void cp_commit() { asm volatile("cp.async.commit_group;"); }
__device__ __forceinline__ void cp_wait_allow(int n) {
    if (n <= 0)      asm volatile("cp.async.wait_group 0;");
    else if (n == 1) asm volatile("cp.async.wait_group 1;");
    else             asm volatile("cp.async.wait_group 2;");
}

// ===========================================================================
// bf16 wmma GEMM: C[M,N] = relu(A @ W^T + bias), bf16 out, fp32 accum.
// CTA 128x128, BK=32, 4-stage cp.async, 8 warps each 64x32.
// LDM=40 bf16 (80B rows): ldmatrix conflict-free. Stage 20480 B, 4 stages.
// ===========================================================================
#define LDM 40
#define STAGE_ELEMS (2 * 128 * LDM)          // 10240 bf16
#define STAGE_BYTES (STAGE_ELEMS * 2)        // 20480
#define GEMM_SMEM   (4 * STAGE_BYTES)        // 81920

__global__ __launch_bounds__(256, 2)
void bf16_gemm(const __nv_bfloat16* __restrict__ A,
               const __nv_bfloat16* __restrict__ W,
               const float* __restrict__ bias,
               __nv_bfloat16* __restrict__ C,
               int N, int K) {
    extern __shared__ __nv_bfloat16 smem[];
    const int tid = threadIdx.x;
    const int warp = tid >> 5;
    const int bm = blockIdx.y * 128;
    const int bn = blockIdx.x * 128;
    const int wm = warp >> 2;
    const int wn = warp & 3;
    const uint32_t sb = smem_u32(smem);

    wmma::fragment<wmma::accumulator, 16, 16, 16, float> cf[4][2];
#pragma unroll
    for (int i = 0; i < 4; i++)
#pragma unroll
        for (int j = 0; j < 2; j++) wmma::fill_fragment(cf[i][j], 0.0f);

    const int T = K / 32;

    // per stage: A 128 rows x 4 chunks(16B) + B same = 1024 cp; 256 thr x 4
    auto load_stage = [&](int t) {
        const int s = t & 3;
        const int k0 = t * 32;
        const uint32_t abase = sb + (uint32_t)s * STAGE_BYTES;
        const uint32_t bbase = abase + 128u * LDM * 2u;
#pragma unroll
        for (int i = 0; i < 2; i++) {
            int idx = tid + i * 256;
            int r = idx >> 2, c = idx & 3;
            CP_ASYNC16(abase + (uint32_t)(r * LDM + c * 8) * 2u,
                       A + (size_t)(bm + r) * K + k0 + c * 8);
        }
#pragma unroll
        for (int i = 0; i < 2; i++) {
            int idx = tid + i * 256;
            int r = idx >> 2, c = idx & 3;
            CP_ASYNC16(bbase + (uint32_t)(r * LDM + c * 8) * 2u,
                       W + (size_t)(bn + r) * K + k0 + c * 8);
        }
        cp_commit();
    };

    const int pre = T < 3 ? T : 3;
    for (int s = 0; s < pre; s++) load_stage(s);

    for (int t = 0; t < T; t++) {
        int allow = T - 1 - t; if (allow > 2) allow = 2;
        cp_wait_allow(allow);        // stage t arrived
        __syncthreads();             // all warps done with stage t-1
        if (t + 3 < T) load_stage(t + 3);   // buf (t+3)&3 == (t-1)&3: safe

        const __nv_bfloat16* a = smem + (size_t)(t & 3) * STAGE_ELEMS;
        const __nv_bfloat16* b = a + 128 * LDM;
#pragma unroll
        for (int kk = 0; kk < 32; kk += 16) {
            wmma::fragment<wmma::matrix_a, 16, 16, 16, __nv_bfloat16, wmma::row_major> af[4];
            wmma::fragment<wmma::matrix_b, 16, 16, 16, __nv_bfloat16, wmma::col_major> bf[2];
#pragma unroll
            for (int i = 0; i < 4; i++)
                wmma::load_matrix_sync(af[i], a + (wm * 64 + i * 16) * LDM + kk, LDM);
#pragma unroll
            for (int j = 0; j < 2; j++)
                wmma::load_matrix_sync(bf[j], b + (wn * 32 + j * 16) * LDM + kk, LDM);
#pragma unroll
            for (int i = 0; i < 4; i++)
#pragma unroll
                for (int j = 0; j < 2; j++)
                    wmma::mma_sync(cf[i][j], af[i], bf[j], cf[i][j]);
        }
    }
    __syncthreads();

    // epilogue: fragments -> smem(fp32 128x132 = 67584 B) -> bf16 gmem
    float* cs = (float*)smem;
#pragma unroll
    for (int i = 0; i < 4; i++)
#pragma unroll
        for (int j = 0; j < 2; j++)
            wmma::store_matrix_sync(cs + (size_t)(wm * 64 + i * 16) * 132 + wn * 32 + j * 16,
                                    cf[i][j], 132, wmma::mem_row_major);
    __syncthreads();

    {
        const int row = tid >> 1, h = tid & 1;
        const float* src = cs + (size_t)row * 132 + h * 64;
        __nv_bfloat16* dst = C + (size_t)(bm + row) * N + bn + h * 64;
        const float* bsrc = bias + bn + h * 64;
#pragma unroll
        for (int q = 0; q < 8; q++) {
            float4 v0 = *(const float4*)(src + q * 8);
            float4 v1 = *(const float4*)(src + q * 8 + 4);
            float4 b0 = *(const float4*)(bsrc + q * 8);
            float4 b1 = *(const float4*)(bsrc + q * 8 + 4);
            v0.x += b0.x; v0.y += b0.y; v0.z += b0.z; v0.w += b0.w;
            v1.x += b1.x; v1.y += b1.y; v1.z += b1.z; v1.w += b1.w;
            v0.x = v0.x > 0.f ? v0.x : 0.f;
            v0.y = v0.y > 0.f ? v0.y : 0.f;
            v0.z = v0.z > 0.f ? v0.z : 0.f;
            v0.w = v0.w > 0.f ? v0.w : 0.f;
            v1.x = v1.x > 0.f ? v1.x : 0.f;
            v1.y = v1.y > 0.f ? v1.y : 0.f;
            v1.z = v1.z > 0.f ? v1.z : 0.f;
            v1.w = v1.w > 0.f ? v1.w : 0.f;
            __nv_bfloat162 p0 = __floats2bfloat162_rn(v0.x, v0.y);
            __nv_bfloat162 p1 = __floats2bfloat162_rn(v0.z, v0.w);
            __nv_bfloat162 p2 = __floats2bfloat162_rn(v1.x, v1.y);
            __nv_bfloat162 p3 = __floats2bfloat162_rn(v1.z, v1.w);
            uint4 pk;
            pk.x = *(uint32_t*)&p0; pk.y = *(uint32_t*)&p1;
            pk.z = *(uint32_t*)&p2; pk.w = *(uint32_t*)&p3;
            *(uint4*)(dst + q * 8) = pk;
        }
    }
}

// ===========================================================================
// fp32 SGEMM for the K=13 bottom layer 1 -> bf16 out.
// ===========================================================================
__global__ __launch_bounds__(256, 2)
void sgemm_l1(const float* __restrict__ A, const float* __restrict__ W,
              const float* __restrict__ bias, __nv_bfloat16* __restrict__ C,
              int N, int K) {
    __shared__ float As[8][132];
    __shared__ float Bs[8][132];
    const int tid = threadIdx.x;
    const int bm = blockIdx.y * 128, bn = blockIdx.x * 128;
    const int tx = tid & 15, ty = tid >> 4;
    const int lk = tid & 7, lr = tid >> 3;

    float acc[8][8];
#pragma unroll
    for (int i = 0; i < 8; i++)
#pragma unroll
        for (int j = 0; j < 8; j++) acc[i][j] = 0.f;

    for (int k0 = 0; k0 < K; k0 += 8) {
        const int kk = k0 + lk;
        const bool kv = (kk < K);
#pragma unroll
        for (int p = 0; p < 4; p++) {
            const int row = lr + p * 32;
            As[lk][row] = kv ? A[(size_t)(bm + row) * K + kk] : 0.f;
            Bs[lk][row] = kv ? W[(size_t)(bn + row) * K + kk] : 0.f;
        }
        __syncthreads();
#pragma unroll
        for (int k = 0; k < 8; k++) {
            float4 a0 = *(const float4*)&As[k][ty * 4];
            float4 a1 = *(const float4*)&As[k][64 + ty * 4];
            float4 b0 = *(const float4*)&Bs[k][tx * 4];
            float4 b1 = *(const float4*)&Bs[k][64 + tx * 4];
            float a[8] = {a0.x, a0.y, a0.z, a0.w, a1.x, a1.y, a1.z, a1.w};
            float b[8] = {b0.x, b0.y, b0.z, b0.w, b1.x, b1.y, b1.z, b1.w};
#pragma unroll
            for (int i = 0; i < 8; i++)
#pragma unroll
                for (int j = 0; j < 8; j++)
                    acc[i][j] += a[i] * b[j];
        }
        __syncthreads();
    }
    const int rbase[2] = {bm + ty * 4, bm + 64 + ty * 4};
    const int cbase[2] = {bn + tx * 4, bn + 64 + tx * 4};
#pragma unroll
    for (int jh = 0; jh < 2; jh++) {
        const int col = cbase[jh];
        float4 bv = *(const float4*)&bias[col];
#pragma unroll
        for (int ih = 0; ih < 2; ih++) {
#pragma unroll
            for (int i = 0; i < 4; i++) {
                const int row = rbase[ih] + i;
                float4 v;
                v.x = acc[ih * 4 + i][jh * 4 + 0] + bv.x;
                v.y = acc[ih * 4 + i][jh * 4 + 1] + bv.y;
                v.z = acc[ih * 4 + i][jh * 4 + 2] + bv.z;
                v.w = acc[ih * 4 + i][jh * 4 + 3] + bv.w;
                v.x = v.x > 0.f ? v.x : 0.f;
                v.y = v.y > 0.f ? v.y : 0.f;
                v.z = v.z > 0.f ? v.z : 0.f;
                v.w = v.w > 0.f ? v.w : 0.f;
                __nv_bfloat162 p0 = __floats2bfloat162_rn(v.x, v.y);
                __nv_bfloat162 p1 = __floats2bfloat162_rn(v.z, v.w);
                uint2 pk; pk.x = *(uint32_t*)&p0; pk.y = *(uint32_t*)&p1;
                *(uint2*)&C[(size_t)row * N + col] = pk;
            }
        }
    }
}

// ===========================================================================
// Interaction via tensor cores. CTA = 256 thr = 8 warps = 8 samples.
// Per sample: feats 32x128 bf16 in smem (rows 27..31 zero), warp computes
// G = F F^T as 2x2 wmma tiles, stages 32x34 fp32 into its own smem patch,
// then emits bottom copy + tril + zero pad.
// smem: 8 * 32 * 136 bf16 = 69632 B (dynamic).
// ===========================================================================
#define IFE 136                           // feats row stride (bf16 elems)
#define INTERACT_SMEM (8 * 32 * IFE * 2)  // 69632

__global__ __launch_bounds__(256)
void interact3(const __nv_bfloat16* __restrict__ bottom,
               const int* __restrict__ cat,
               const float* __restrict__ emb,
               __nv_bfloat16* __restrict__ x) {
    extern __shared__ __nv_bfloat16 ism[];
    const int tid = threadIdx.x;
    const int warp = tid >> 5, lane = tid & 31;
    const int b0 = blockIdx.x * 8;

    // zero pad rows 27..31 of each sample (8*5*IFE = 5440 bf16)
    for (int i = tid; i < 8 * 5 * IFE; i += 256) {
        int s = i / (5 * IFE), rem = i % (5 * IFE);
        ism[(size_t)(s * 32 + 27) * IFE + rem] = __float2bfloat16(0.f);
    }

    // gather: 8 samples x 27 rows x 32 f4-chunks = 6912
    for (int idx = tid; idx < 8 * 27 * 32; idx += 256) {
        const int s = idx / 864;
        const int rem = idx % 864;
        const int r = rem >> 5, q = rem & 31;
        const int b = b0 + s;
        __nv_bfloat16* drow = ism + (size_t)(s * 32 + r) * IFE + q * 4;
        if (r == 0) {
            *(uint2*)drow = *(const uint2*)(bottom + (size_t)b * 128 + q * 4);
        } else {
            const int ci = cat[(size_t)(r - 1) * BATCH + b];
            float4 v = *(const float4*)(emb + ((size_t)(r - 1) * TABLE_SIZE + ci) * 128 + q * 4);
            __nv_bfloat162 p0 = __floats2bfloat162_rn(v.x, v.y);
            __nv_bfloat162 p1 = __floats2bfloat162_rn(v.z, v.w);
            uint2 pk; pk.x = *(uint32_t*)&p0; pk.y = *(uint32_t*)&p1;
            *(uint2*)drow = pk;
        }
    }
    __syncthreads();

    // warp-per-sample gram
    const __nv_bfloat16* fb = ism + (size_t)warp * 32 * IFE;
    wmma::fragment<wmma::accumulator, 16, 16, 16, float> gc[2][2];
#pragma unroll
    for (int i = 0; i < 2; i++)
#pragma unroll
        for (int j = 0; j < 2; j++) wmma::fill_fragment(gc[i][j], 0.0f);

#pragma unroll
    for (int kk = 0; kk < 128; kk += 16) {
        wmma::fragment<wmma::matrix_a, 16, 16, 16, __nv_bfloat16, wmma::row_major> af[2];
        wmma::fragment<wmma::matrix_b, 16, 16, 16, __nv_bfloat16, wmma::col_major> bf[2];
        wmma::load_matrix_sync(af[0], fb + kk, IFE);
        wmma::load_matrix_sync(af[1], fb + 16 * IFE + kk, IFE);
        wmma::load_matrix_sync(bf[0], fb + kk, IFE);
        wmma::load_matrix_sync(bf[1], fb + 16 * IFE + kk, IFE);
#pragma unroll
        for (int i = 0; i < 2; i++)
#pragma unroll
            for (int j = 0; j < 2; j++)
                wmma::mma_sync(gc[i][j], af[i], bf[j], gc[i][j]);
    }

    // stage G into this warp's own smem patch (32x34 fp32 = 4352 B <= 8704)
    float* gs = (float*)(ism + (size_t)warp * 32 * IFE);
#pragma unroll
    for (int i = 0; i < 2; i++)
#pragma unroll
        for (int j = 0; j < 2; j++)
            wmma::store_matrix_sync(gs + (size_t)i * 16 * 34 + j * 16,
                                    gc[i][j], 34, wmma::mem_row_major);
    __syncwarp();

    // output
    const int b = b0 + warp;
    __nv_bfloat16* xb = x + (size_t)b * TOP_IN_P;
    if (lane < 16) {
        *(uint4*)(xb + lane * 8) = *(const uint4*)(bottom + (size_t)b * 128 + lane * 8);
    } else if (lane < 20) {
        uint4 z; z.x = z.y = z.z = z.w = 0u;
        *(uint4*)(xb + 480 + (lane - 16) * 8) = z;
    } else if (lane == 20) {
        xb[TOP_IN - 1] = __float2bfloat16(0.f);
    }
    for (int p = lane; p < 351; p += 32) {
        int r = 1;
        while (r * (r + 1) / 2 <= p) r++;
        const int c = p - r * (r - 1) / 2;
        xb[128 + p] = __float2bfloat16(gs[r * 34 + c]);
    }
}

// ===========================================================================
// One kernel rounding all weights to bf16 (tw1 zero-padded K 480->512).
// ===========================================================================
#define RW_N0 131072
#define RW_N1 32768
#define RW_N2 (1024 * TOP_IN_P)
#define RW_N3 1048576
#define RW_N4 524288
#define RW_N5 131072
#define RW_TOTAL (RW_N0 + RW_N1 + RW_N2 + RW_N3 + RW_N4 + RW_N5)

__global__ __launch_bounds__(256)
void round_all(const float* __restrict__ bw2, const float* __restrict__ bw3,
               const float* __restrict__ tw1, const float* __restrict__ tw2,
               const float* __restrict__ tw3, const float* __restrict__ tw4,
               __nv_bfloat16* __restrict__ d0, __nv_bfloat16* __restrict__ d1,
               __nv_bfloat16* __restrict__ d2, __nv_bfloat16* __restrict__ d3,
               __nv_bfloat16* __restrict__ d4, __nv_bfloat16* __restrict__ d5) {
    int i = blockIdx.x * blockDim.x + threadIdx.x;
    if (i >= RW_TOTAL) return;
    if (i < RW_N0) { d0[i] = __float2bfloat16(bw2[i]); return; }
    i -= RW_N0;
    if (i < RW_N1) { d1[i] = __float2bfloat16(bw3[i]); return; }
    i -= RW_N1;
    if (i < RW_N2) {
        int n = i / TOP_IN_P, k = i % TOP_IN_P;
        d2[i] = (k < TOP_IN) ? __float2bfloat16(tw1[n * TOP_IN + k])
                             : __float2bfloat16(0.f);
        return;
    }
    i -= RW_N2;
    if (i < RW_N3) { d3[i] = __float2bfloat16(tw2[i]); return; }
    i -= RW_N3;
    if (i < RW_N4) { d4[i] = __float2bfloat16(tw3[i]); return; }
    i -= RW_N4;
    d5[i] = __float2bfloat16(tw4[i]);
}

// ===========================================================================
// Final layer: sigmoid(dot(t4_bf16, w5) + b5). Warp per sample.
// ===========================================================================
__global__ __launch_bounds__(256)
void final_layer(const __nv_bfloat16* __restrict__ A,
                 const float* __restrict__ w5,
                 const float* __restrict__ b5, float* __restrict__ out) {
    const int gwarp = (blockIdx.x * blockDim.x + threadIdx.x) >> 5;
    const int lane = threadIdx.x & 31;
    if (gwarp >= BATCH) return;
    uint4 raw = *(const uint4*)(A + (size_t)gwarp * 256 + lane * 8);
    const float4* w4 = (const float4*)(w5 + lane * 8);
    float4 w0 = w4[0], w1 = w4[1];
    __nv_bfloat162 p0 = *(__nv_bfloat162*)&raw.x;
    __nv_bfloat162 p1 = *(__nv_bfloat162*)&raw.y;
    __nv_bfloat162 p2 = *(__nv_bfloat162*)&raw.z;
    __nv_bfloat162 p3 = *(__nv_bfloat162*)&raw.w;
    float s = __bfloat162float(p0.x) * w0.x + __bfloat162float(p0.y) * w0.y +
              __bfloat162float(p1.x) * w0.z + __bfloat162float(p1.y) * w0.w +
              __bfloat162float(p2.x) * w1.x + __bfloat162float(p2.y) * w1.y +
              __bfloat162float(p3.x) * w1.z + __bfloat162float(p3.y) * w1.w;
#pragma unroll
    for (int o = 16; o; o >>= 1) s += __shfl_xor_sync(0xffffffffu, s, o);
    if (lane == 0) out[gwarp] = 1.f / (1.f + expf(-(s + b5[0])));
}

// ===========================================================================
extern "C" void kernel_launch(void* const* d_in, const int* in_sizes, int n_in,
                              void* d_out, int out_size) {
    const float* num = (const float*)d_in[0];
    const int*   cat = (const int*)  d_in[1];
    const float* emb = (const float*)d_in[2];
    const float* bw1 = (const float*)d_in[3];
    const float* bb1 = (const float*)d_in[4];
    const float* bw2 = (const float*)d_in[5];
    const float* bb2 = (const float*)d_in[6];
    const float* bw3 = (const float*)d_in[7];
    const float* bb3 = (const float*)d_in[8];
    const float* tw1 = (const float*)d_in[9];
    const float* tb1 = (const float*)d_in[10];
    const float* tw2 = (const float*)d_in[11];
    const float* tb2 = (const float*)d_in[12];
    const float* tw3 = (const float*)d_in[13];
    const float* tb3 = (const float*)d_in[14];
    const float* tw4 = (const float*)d_in[15];
    const float* tb4 = (const float*)d_in[16];
    const float* tw5 = (const float*)d_in[17];
    const float* tb5 = (const float*)d_in[18];
    float* out = (float*)d_out;

    __nv_bfloat16 *h1, *h2, *bot, *x, *t1, *t2, *t3, *t4;
    __nv_bfloat16 *bw2r, *bw3r, *tw1r, *tw2r, *tw3r, *tw4r;
    cudaGetSymbolAddress((void**)&h1,  g_h1);
    cudaGetSymbolAddress((void**)&h2,  g_h2);
    cudaGetSymbolAddress((void**)&bot, g_bot);
    cudaGetSymbolAddress((void**)&x,   g_x);
    cudaGetSymbolAddress((void**)&t1,  g_t1);
    cudaGetSymbolAddress((void**)&t2,  g_t2);
    cudaGetSymbolAddress((void**)&t3,  g_t3);
    cudaGetSymbolAddress((void**)&t4,  g_t4);
    cudaGetSymbolAddress((void**)&bw2r, g_bw2r);
    cudaGetSymbolAddress((void**)&bw3r, g_bw3r);
    cudaGetSymbolAddress((void**)&tw1r, g_tw1r);
    cudaGetSymbolAddress((void**)&tw2r, g_tw2r);
    cudaGetSymbolAddress((void**)&tw3r, g_tw3r);
    cudaGetSymbolAddress((void**)&tw4r, g_tw4r);

    cudaFuncSetAttribute(bf16_gemm, cudaFuncAttributeMaxDynamicSharedMemorySize, GEMM_SMEM);
    cudaFuncSetAttribute(interact3, cudaFuncAttributeMaxDynamicSharedMemorySize, INTERACT_SMEM);

    round_all<<<(RW_TOTAL + 255) / 256, 256>>>(bw2, bw3, tw1, tw2, tw3, tw4,
                                               bw2r, bw3r, tw1r, tw2r, tw3r, tw4r);

    const int MB = BATCH / 128;  // 128

    // bottom MLP
    sgemm_l1<<<dim3(4, MB), 256>>>(num, bw1, bb1, h1, 512, 13);
    bf16_gemm<<<dim3(2, MB), 256, GEMM_SMEM>>>(h1, bw2r, bb2, h2, 256, 512);
    bf16_gemm<<<dim3(1, MB), 256, GEMM_SMEM>>>(h2, bw3r, bb3, bot, 128, 256);

    // interaction (tensor-core gram)
    interact3<<<BATCH / 8, 256, INTERACT_SMEM>>>(bot, cat, emb, x);

    // top MLP
    bf16_gemm<<<dim3(8, MB), 256, GEMM_SMEM>>>(x,  tw1r, tb1, t1, 1024, TOP_IN_P);
    bf16_gemm<<<dim3(8, MB), 256, GEMM_SMEM>>>(t1, tw2r, tb2, t2, 1024, 1024);
    bf16_gemm<<<dim3(4, MB), 256, GEMM_SMEM>>>(t2, tw3r, tb3, t3, 512, 1024);
    bf16_gemm<<<dim3(2, MB), 256, GEMM_SMEM>>>(t3, tw4r, tb4, t4, 256, 512);

    // final dot + sigmoid
    final_layer<<<(BATCH * 32 + 255) / 256, 256>>>(t4, tw5, tb5, out);
}